// round 7
// baseline (speedup 1.0000x reference)
#include <cuda_runtime.h>
#include <cuda_bf16.h>
#include <cstdint>

#define B_ 4
#define S_ 4096
#define D_ 512
#define M1 (B_*S_)   // 16384

// ---------------- scratch (device globals: the sanctioned no-alloc path) ----
__device__ float         g_K   [B_*S_*D_];
__device__ float         g_Q   [B_*S_*D_];
__device__ float         g_VL  [B_*S_*D_];
__device__ __nv_bfloat16 g_E   [(size_t)B_*S_*S_];   // exp(qk/512), bf16
__device__ float         g_part[B_*8*S_];            // partial column sums
__device__ float         g_Linv[B_*S_];
__device__ float         g_r   [B_*S_];
__device__ float         g_Wc  [D_*D_];
__device__ float         g_bc  [D_];

// ---------------- helpers ---------------------------------------------------
__device__ __forceinline__ uint32_t f2tf(float x){
    uint32_t r; asm("cvt.rna.tf32.f32 %0, %1;" : "=r"(r) : "f"(x)); return r;
}
__device__ __forceinline__ void mma8(float c[4], const uint32_t a[4], const uint32_t b[2]){
    asm volatile(
        "mma.sync.aligned.m16n8k8.row.col.f32.tf32.tf32.f32 "
        "{%0,%1,%2,%3}, {%4,%5,%6,%7}, {%8,%9}, {%0,%1,%2,%3};"
        : "+f"(c[0]), "+f"(c[1]), "+f"(c[2]), "+f"(c[3])
        : "r"(a[0]), "r"(a[1]), "r"(a[2]), "r"(a[3]), "r"(b[0]), "r"(b[1]));
}

// ---------------- Wc = Wl @ Wv (fp32, tiny) ---------------------------------
__global__ void wc_gemm(const float* __restrict__ Wl, const float* __restrict__ Wv,
                        float* __restrict__ Wc){
    __shared__ float sL[16][16];
    __shared__ float sV[16][17];
    int j = blockIdx.y*16 + threadIdx.y;
    int i = blockIdx.x*16 + threadIdx.x;
    float acc = 0.f;
    for (int k0 = 0; k0 < D_; k0 += 16){
        sL[threadIdx.y][threadIdx.x] = Wl[j*D_ + k0 + threadIdx.x];
        sV[threadIdx.y][threadIdx.x] = Wv[(k0 + threadIdx.y)*D_ + i];
        __syncthreads();
        #pragma unroll
        for (int k = 0; k < 16; k++) acc += sL[threadIdx.y][k]*sV[k][threadIdx.x];
        __syncthreads();
    }
    Wc[j*D_ + i] = acc;
}

// ---------------- bc = Wl @ bv ----------------------------------------------
__global__ void bc_kernel(const float* __restrict__ Wl, const float* __restrict__ bv,
                          float* __restrict__ bc){
    int j = blockIdx.x;
    __shared__ float red[128];
    float a = 0.f;
    for (int k = threadIdx.x; k < D_; k += 128) a += Wl[j*D_ + k]*bv[k];
    red[threadIdx.x] = a; __syncthreads();
    for (int s = 64; s > 0; s >>= 1){
        if (threadIdx.x < s) red[threadIdx.x] += red[threadIdx.x + s];
        __syncthreads();
    }
    if (threadIdx.x == 0) bc[j] = red[0];
}

// ---------------- generic tf32 mma GEMM: C = A @ B^T (+epilogue) ------------
// A: [M,K] rm, B: [N,K] rm. All of M,N divisible by 128, K by 32 (true here).
// EPI 0: Cf[m,n] = acc + bias[n]            (fp32 out, ldc = N)
// EPI 1: Cb[m,n] = bf16(exp(acc/512))       (bf16 out, ldc = N)
#define BMT 128
#define BNT 128
#define BKT 32
#define LDT 36   // (BKT+4): (36 mod 32)==4 makes all fragment LDS conflict-free

template<int EPI>
__global__ void __launch_bounds__(256, 2)
gemm_tf32(const float* __restrict__ Ag, const float* __restrict__ Bg,
          const float* __restrict__ bias,
          float* __restrict__ Cf, __nv_bfloat16* __restrict__ Cb,
          int M, int N, int K,
          long long strA, long long strB, long long strC)
{
    __shared__ uint32_t sA[BMT*LDT];
    __shared__ uint32_t sB[BNT*LDT];

    const int tid  = threadIdx.x;
    const long long bz = blockIdx.z;
    const float* A  = Ag + bz*strA;
    const float* Bm = Bg + bz*strB;
    const int bm = blockIdx.y*BMT, bn = blockIdx.x*BNT;
    const int lane = tid & 31, warp = tid >> 5;
    const int wm = (warp & 1)*64, wn = (warp >> 1)*32;  // 2x4 warp grid, 64x32 tiles
    const int g = lane >> 2, t = lane & 3;
    const int lrow = tid >> 3, lcol = (tid & 7)*4;

    float acc[4][4][4];
    #pragma unroll
    for (int i = 0; i < 4; i++)
        #pragma unroll
        for (int j = 0; j < 4; j++)
            #pragma unroll
            for (int c = 0; c < 4; c++) acc[i][j][c] = 0.f;

    for (int k0 = 0; k0 < K; k0 += BKT){
        #pragma unroll
        for (int p = 0; p < 4; p++){
            int r = lrow + p*32;
            float4 va = *(const float4*)(A  + (long long)(bm + r)*K + k0 + lcol);
            uint32_t* da = &sA[r*LDT + lcol];
            da[0] = f2tf(va.x); da[1] = f2tf(va.y); da[2] = f2tf(va.z); da[3] = f2tf(va.w);
            float4 vb = *(const float4*)(Bm + (long long)(bn + r)*K + k0 + lcol);
            uint32_t* db = &sB[r*LDT + lcol];
            db[0] = f2tf(vb.x); db[1] = f2tf(vb.y); db[2] = f2tf(vb.z); db[3] = f2tf(vb.w);
        }
        __syncthreads();
        #pragma unroll
        for (int kk = 0; kk < BKT; kk += 8){
            uint32_t af[4][4], bf[4][2];
            #pragma unroll
            for (int mi = 0; mi < 4; mi++){
                int r = wm + mi*16 + g;
                af[mi][0] = sA[ r    *LDT + kk + t    ];
                af[mi][1] = sA[(r+8) *LDT + kk + t    ];
                af[mi][2] = sA[ r    *LDT + kk + t + 4];
                af[mi][3] = sA[(r+8) *LDT + kk + t + 4];
            }
            #pragma unroll
            for (int ni = 0; ni < 4; ni++){
                int rn = wn + ni*8 + g;
                bf[ni][0] = sB[rn*LDT + kk + t    ];
                bf[ni][1] = sB[rn*LDT + kk + t + 4];
            }
            #pragma unroll
            for (int mi = 0; mi < 4; mi++)
                #pragma unroll
                for (int ni = 0; ni < 4; ni++)
                    mma8(acc[mi][ni], af[mi], bf[ni]);
        }
        __syncthreads();
    }

    // epilogue
    #pragma unroll
    for (int mi = 0; mi < 4; mi++){
        int r0 = bm + wm + mi*16 + g;
        #pragma unroll
        for (int ni = 0; ni < 4; ni++){
            int c = bn + wn + ni*8 + 2*t;
            float* ac = acc[mi][ni];
            if (EPI == 0){
                float b0 = bias[c], b1 = bias[c+1];
                *(float2*)(Cf + (long long)r0*N + c)     = make_float2(ac[0]+b0, ac[1]+b1);
                *(float2*)(Cf + (long long)(r0+8)*N + c) = make_float2(ac[2]+b0, ac[3]+b1);
            } else {
                __nv_bfloat16* Co = Cb + bz*strC;
                const float inv = 1.0f/512.0f;
                *(__nv_bfloat162*)(Co + (long long)r0*N + c) =
                    __floats2bfloat162_rn(__expf(ac[0]*inv), __expf(ac[1]*inv));
                *(__nv_bfloat162*)(Co + (long long)(r0+8)*N + c) =
                    __floats2bfloat162_rn(__expf(ac[2]*inv), __expf(ac[3]*inv));
            }
        }
    }
}

// ---------------- column-sum partials (deterministic, no atomics) -----------
__global__ void colsum_part(const __nv_bfloat16* __restrict__ E, float* __restrict__ part){
    int e = blockIdx.x*256 + threadIdx.x;
    int chunk = blockIdx.y, b = blockIdx.z;
    const __nv_bfloat16* p = E + (long long)b*S_*S_ + (long long)chunk*512*S_ + e;
    float acc = 0.f;
    #pragma unroll 8
    for (int s = 0; s < 512; s++) acc += __bfloat162float(p[(long long)s*S_]);
    part[(b*8 + chunk)*S_ + e] = acc;
}

__global__ void linv_kernel(const float* __restrict__ part, float* __restrict__ Linv){
    int i = blockIdx.x*256 + threadIdx.x;          // b*S + e, 16384 total
    int b = i >> 12, e = i & (S_-1);
    float s = 0.f;
    #pragma unroll
    for (int c = 0; c < 8; c++) s += part[(b*8 + c)*S_ + e];
    Linv[i] = 1.0f / s;
}

// ---------------- row-sum of E * Linv ---------------------------------------
__global__ void rowsum_kernel(const __nv_bfloat16* __restrict__ E,
                              const float* __restrict__ Linv, float* __restrict__ r){
    int s = blockIdx.x, b = blockIdx.y, tid = threadIdx.x;
    const __nv_bfloat162* row2 = (const __nv_bfloat162*)(E + ((long long)b*S_ + s)*S_);
    const float2* li2 = (const float2*)(Linv + b*S_);
    float acc = 0.f;
    #pragma unroll 4
    for (int i = tid; i < S_/2; i += 256){
        float2 v = __bfloat1622float2(row2[i]);
        float2 l = li2[i];
        acc += v.x*l.x + v.y*l.y;
    }
    __shared__ float red[256];
    red[tid] = acc; __syncthreads();
    for (int st = 128; st > 0; st >>= 1){
        if (tid < st) red[tid] += red[tid + st];
        __syncthreads();
    }
    if (tid == 0) r[(long long)b*S_ + s] = red[0];
}

// ---------------- out = tanh(r * VL + bl) -----------------------------------
__global__ void out_kernel(const float* __restrict__ VL, const float* __restrict__ r,
                           const float* __restrict__ bl, float* __restrict__ out){
    long long i = (long long)blockIdx.x*256 + threadIdx.x;   // one float4 each
    float4 v = ((const float4*)VL)[i];
    float rv = r[i >> 7];                                    // (4i)/512
    float4 b4 = ((const float4*)bl)[(int)(i & 127)];         // (4i mod 512)/4
    float4 o;
    o.x = tanhf(rv*v.x + b4.x);
    o.y = tanhf(rv*v.y + b4.y);
    o.z = tanhf(rv*v.z + b4.z);
    o.w = tanhf(rv*v.w + b4.w);
    ((float4*)out)[i] = o;
}

// ---------------- launcher --------------------------------------------------
extern "C" void kernel_launch(void* const* d_in, const int* in_sizes, int n_in,
                              void* d_out, int out_size){
    const float* xs = (const float*)d_in[0];
    const float* Wk = (const float*)d_in[1];
    const float* bk = (const float*)d_in[2];
    const float* Wq = (const float*)d_in[3];
    const float* bq = (const float*)d_in[4];
    const float* Wv = (const float*)d_in[5];
    const float* bv = (const float*)d_in[6];
    const float* Wl = (const float*)d_in[7];
    const float* bl = (const float*)d_in[8];
    float* out = (float*)d_out;
    (void)in_sizes; (void)n_in; (void)out_size; (void)Wv; (void)bv;

    float *pK, *pQ, *pVL, *pPart, *pLinv, *pR, *pWc, *pBc;
    __nv_bfloat16* pE;
    cudaGetSymbolAddress((void**)&pK,    g_K);
    cudaGetSymbolAddress((void**)&pQ,    g_Q);
    cudaGetSymbolAddress((void**)&pVL,   g_VL);
    cudaGetSymbolAddress((void**)&pE,    g_E);
    cudaGetSymbolAddress((void**)&pPart, g_part);
    cudaGetSymbolAddress((void**)&pLinv, g_Linv);
    cudaGetSymbolAddress((void**)&pR,    g_r);
    cudaGetSymbolAddress((void**)&pWc,   g_Wc);
    cudaGetSymbolAddress((void**)&pBc,   g_bc);

    // 1) combined last-layer weights: Wc = Wl@Wv, bc = Wl@bv
    wc_gemm<<<dim3(D_/16, D_/16), dim3(16,16)>>>(Wl, Wv, pWc);
    bc_kernel<<<D_, 128>>>(Wl, bv, pBc);

    // 2) K, Q, VL = xs @ {Wk,Wq,Wc}^T + {bk,bq,bc}   ([16384,512]x[512,512]^T)
    gemm_tf32<0><<<dim3(D_/BNT, M1/BMT, 1), 256>>>(xs, Wk,  bk,  pK,  nullptr,
                                                   M1, D_, D_, 0, 0, 0);
    gemm_tf32<0><<<dim3(D_/BNT, M1/BMT, 1), 256>>>(xs, Wq,  bq,  pQ,  nullptr,
                                                   M1, D_, D_, 0, 0, 0);
    gemm_tf32<0><<<dim3(D_/BNT, M1/BMT, 1), 256>>>(xs, pWc, pBc, pVL, nullptr,
                                                   M1, D_, D_, 0, 0, 0);

    // 3) E[b] = exp((K[b] @ Q[b]^T)/512), bf16   (batched over grid.z)
    gemm_tf32<1><<<dim3(S_/BNT, S_/BMT, B_), 256>>>(pK, pQ, nullptr, nullptr, pE,
                                                    S_, S_, D_,
                                                    (long long)S_*D_, (long long)S_*D_,
                                                    (long long)S_*S_);

    // 4) Linv[b,e] = 1 / sum_s E ;  r[b,s] = sum_e E * Linv
    colsum_part<<<dim3(S_/256, 8, B_), 256>>>(pE, pPart);
    linv_kernel<<<(B_*S_)/256, 256>>>(pPart, pLinv);
    rowsum_kernel<<<dim3(S_, B_), 256>>>(pE, pLinv, pR);

    // 5) out = tanh(r * VL + bl)
    out_kernel<<<(B_*S_*D_/4)/256, 256>>>(pVL, pR, bl, out);
}